// round 5
// baseline (speedup 1.0000x reference)
#include <cuda_runtime.h>
#include <cuda_bf16.h>
#include <cuda_fp16.h>
#include <math.h>
#include <stdint.h>

#define S_LEN 1024
#define BATCH 2
#define HDIM  1024
#define EDIM  512
#define VDIM  32000
#define MDIM  128

// ---------------- scratch (device globals; no allocations) ----------------
__device__ float g_xg[BATCH * S_LEN * 3 * HDIM];
__device__ float g_states[BATCH * S_LEN * HDIM];
__device__ float g_q[BATCH * S_LEN * MDIM];
__device__ float g_k[BATCH * S_LEN * MDIM];
__device__ float g_gate[BATCH * S_LEN];
__device__ float g_hbuf[2 * BATCH * HDIM];
__device__ unsigned int g_bar;
__device__ unsigned int g_rel;

// split fp16 operand storage
__device__ __align__(16) __half g_emb_h[VDIM * EDIM];
__device__ __align__(16) __half g_emb_l[VDIM * EDIM];
__device__ __align__(16) __half g_wih_h[3 * HDIM * EDIM];
__device__ __align__(16) __half g_wih_l[3 * HDIM * EDIM];
__device__ __align__(16) __half g_wfc_h[4 * EDIM * HDIM];
__device__ __align__(16) __half g_wfc_l[4 * EDIM * HDIM];
__device__ __align__(16) __half g_wpr_h[EDIM * 4 * EDIM];
__device__ __align__(16) __half g_wpr_l[EDIM * 4 * EDIM];
__device__ __align__(16) __half g_ns_h[BATCH * S_LEN * HDIM];
__device__ __align__(16) __half g_ns_l[BATCH * S_LEN * HDIM];
__device__ __align__(16) __half g_hf_h[BATCH * S_LEN * 4 * EDIM];
__device__ __align__(16) __half g_hf_l[BATCH * S_LEN * 4 * EDIM];
__device__ __align__(16) __half g_base_h[BATCH * S_LEN * EDIM];
__device__ __align__(16) __half g_base_l[BATCH * S_LEN * EDIM];

// ---------------- init ----------------
__global__ void init_kernel() {
    int t = blockIdx.x * blockDim.x + threadIdx.x;
    if (t == 0) { g_bar = 0u; g_rel = 0u; }
    if (t < 2 * BATCH * HDIM) g_hbuf[t] = 0.f;
}

// ---------------- fp32 -> (hi, lo) fp16 splitter ----------------
__global__ void split_kernel(const float4* __restrict__ src,
                             uint2* __restrict__ hi, uint2* __restrict__ lo, int n4) {
    for (int i = blockIdx.x * blockDim.x + threadIdx.x; i < n4; i += gridDim.x * blockDim.x) {
        float4 v = src[i];
        __half2 h01 = __floats2half2_rn(v.x, v.y);
        __half2 h23 = __floats2half2_rn(v.z, v.w);
        float2 b01 = __half22float2(h01);
        float2 b23 = __half22float2(h23);
        __half2 l01 = __floats2half2_rn(v.x - b01.x, v.y - b01.y);
        __half2 l23 = __floats2half2_rn(v.z - b23.x, v.w - b23.y);
        hi[i] = make_uint2(*(uint32_t*)&h01, *(uint32_t*)&h23);
        lo[i] = make_uint2(*(uint32_t*)&l01, *(uint32_t*)&l23);
    }
}

// ================= PTX helpers =================
__device__ __forceinline__ uint32_t smem_u32(const void* p) {
    uint32_t a;
    asm("{ .reg .u64 t; cvta.to.shared.u64 t, %1; cvt.u32.u64 %0, t; }" : "=r"(a) : "l"(p));
    return a;
}
__device__ __forceinline__ void ldsm4(uint32_t* r, uint32_t addr) {
    asm volatile("ldmatrix.sync.aligned.m8n8.x4.shared.b16 {%0,%1,%2,%3}, [%4];"
                 : "=r"(r[0]), "=r"(r[1]), "=r"(r[2]), "=r"(r[3]) : "r"(addr));
}
__device__ __forceinline__ void mma16816(float* d, const uint32_t* a, const uint32_t* b) {
    asm volatile(
        "mma.sync.aligned.m16n8k16.row.col.f32.f16.f16.f32 "
        "{%0,%1,%2,%3}, {%4,%5,%6,%7}, {%8,%9}, {%0,%1,%2,%3};"
        : "+f"(d[0]), "+f"(d[1]), "+f"(d[2]), "+f"(d[3])
        : "r"(a[0]), "r"(a[1]), "r"(a[2]), "r"(a[3]), "r"(b[0]), "r"(b[1]));
}
__device__ __forceinline__ void cp16(uint32_t saddr, const void* gptr) {
    asm volatile("cp.async.cg.shared.global [%0], [%1], 16;" :: "r"(saddr), "l"(gptr));
}
#define CP_COMMIT() asm volatile("cp.async.commit_group;" ::: "memory")
#define CP_WAIT_GROUP(N) asm volatile("cp.async.wait_group %0;" :: "n"(N) : "memory")

// ======== cp.async pipelined fp16 GEMM: C[M,N] = A[M,K] @ B[N,K]^T + bias ========
// operands pre-split (hi+lo fp16). TERMS=3: ah*bh + ah*bl + al*bh (err ~2^-22)
//                                  TERMS=2: ah*bh + al*bh = a*bh  (err ~2^-11 of B)
// grid=(N/128, M/128), 256 thr (8 warps 4x2). K%32==0. smem rows 80B (ldmatrix conflict-free).
#define MT_STRIDE  80
#define MT_MAT     (128 * MT_STRIDE)       // 10240
#define MT_STAGE   (4 * MT_MAT)            // Ah, Al, Bh, Bl slots = 40960
#define MT_NSTAGE  3
#define MT_SMEM_TOTAL (1024 + MT_NSTAGE * MT_STAGE)  // 123904

// EPI: 0 = fp32 out (bias add), 1 = split fp16 out with relu^2, 2 = split fp16 out plain
template <int TERMS, bool GATHER>
__device__ __forceinline__ void issue_chunk(
    uint32_t sbuf, const __half* Ah, const __half* Al,
    const __half* Bh, const __half* Bl,
    int K, int k0, int m0, int n0, const int* s_ids, int tid)
{
#pragma unroll
    for (int i = 0; i < 2; i++) {
        int u = (tid << 1) + i;             // 0..511
        int r = u >> 2, seg = u & 3;
        int arow = GATHER ? s_ids[r] : (m0 + r);
        size_t aoff = (size_t)arow * K + k0 + seg * 8;
        size_t boff = (size_t)(n0 + r) * K + k0 + seg * 8;
        uint32_t so = sbuf + r * MT_STRIDE + seg * 16;
        cp16(so,              Ah + aoff);
        cp16(so + MT_MAT,     Al + aoff);
        cp16(so + 2 * MT_MAT, Bh + boff);
        if (TERMS == 3) cp16(so + 3 * MT_MAT, Bl + boff);
    }
}

template <int TERMS, int EPI, bool GATHER>
__global__ void __launch_bounds__(256, 1) mma_gemm(
    const __half* __restrict__ Ah, const __half* __restrict__ Al,
    const __half* __restrict__ Bh, const __half* __restrict__ Bl,
    const float* __restrict__ bias, float* __restrict__ Cf,
    __half* __restrict__ Ch, __half* __restrict__ Cl,
    int N, int K, const int* __restrict__ gidx)
{
    extern __shared__ __align__(128) char smem[];
    const uint32_t smb = smem_u32(smem);
    const int tid = threadIdx.x;
    const int wid = tid >> 5, lane = tid & 31;
    const int wm = wid & 3, wn = wid >> 2;
    const int m0 = blockIdx.y * 128, n0 = blockIdx.x * 128;
    int* s_ids = (int*)smem;

    if (GATHER && tid < 128) s_ids[tid] = gidx[m0 + tid];
    __syncthreads();

    float d[2][8][4];
#pragma unroll
    for (int i = 0; i < 2; i++)
#pragma unroll
        for (int j = 0; j < 8; j++)
#pragma unroll
            for (int c = 0; c < 4; c++) d[i][j][c] = 0.f;

    const int nc = K >> 5;

    // prologue: stages 0 and 1 in flight
    issue_chunk<TERMS, GATHER>(smb + 1024, Ah, Al, Bh, Bl, K, 0, m0, n0, s_ids, tid);
    CP_COMMIT();
    if (nc > 1)
        issue_chunk<TERMS, GATHER>(smb + 1024 + MT_STAGE, Ah, Al, Bh, Bl, K, 32, m0, n0, s_ids, tid);
    CP_COMMIT();

    int st = 0;          // stage of chunk s
    int stn = 2;         // stage of chunk s+2
    for (int s = 0; s < nc; s++) {
        CP_WAIT_GROUP(1);          // chunk s resident
        __syncthreads();           // visible to all; stage (s-1)%3 reads done
        if (s + 2 < nc)
            issue_chunk<TERMS, GATHER>(smb + 1024 + stn * MT_STAGE, Ah, Al, Bh, Bl,
                                       K, (s + 2) << 5, m0, n0, s_ids, tid);
        CP_COMMIT();

        const uint32_t buf = smb + 1024 + st * MT_STAGE;
#pragma unroll
        for (int h = 0; h < 2; h++) {
            const int k16 = h * 16;
            uint32_t ah[2][4], al[2][4], bh[4][4], bl[4][4];
#pragma unroll
            for (int mt = 0; mt < 2; mt++) {
                uint32_t addr = buf + (wm * 32 + mt * 16 + (lane & 15)) * MT_STRIDE
                              + (k16 + (lane >> 4) * 8) * 2;
                ldsm4(ah[mt], addr);
                ldsm4(al[mt], addr + MT_MAT);
            }
#pragma unroll
            for (int p = 0; p < 4; p++) {
                int nrow = wn * 64 + p * 16 + (lane & 7) + ((lane >> 4) & 1) * 8;
                int kk = k16 + ((lane >> 3) & 1) * 8;
                uint32_t addr = buf + 2 * MT_MAT + nrow * MT_STRIDE + kk * 2;
                ldsm4(bh[p], addr);
                if (TERMS == 3) ldsm4(bl[p], addr + MT_MAT);
            }
#pragma unroll
            for (int mt = 0; mt < 2; mt++)
#pragma unroll
                for (int nt = 0; nt < 8; nt++) {
                    const uint32_t* bhp = &bh[nt >> 1][(nt & 1) * 2];
                    mma16816(d[mt][nt], ah[mt], bhp);
                    mma16816(d[mt][nt], al[mt], bhp);
                    if (TERMS == 3) {
                        const uint32_t* blp = &bl[nt >> 1][(nt & 1) * 2];
                        mma16816(d[mt][nt], ah[mt], blp);
                    }
                }
        }
        st = (st + 1 == 3) ? 0 : st + 1;
        stn = (stn + 1 == 3) ? 0 : stn + 1;
    }

    // epilogue
#pragma unroll
    for (int mt = 0; mt < 2; mt++) {
        const int row = m0 + wm * 32 + mt * 16 + (lane >> 2);
#pragma unroll
        for (int nt = 0; nt < 8; nt++) {
            const int col = n0 + wn * 64 + nt * 8 + (lane & 3) * 2;
            float b0 = bias[col], b1 = bias[col + 1];
            float x0 = d[mt][nt][0] + b0, x1 = d[mt][nt][1] + b1;
            float x2 = d[mt][nt][2] + b0, x3 = d[mt][nt][3] + b1;
            if (EPI == 1) {
                x0 = fmaxf(x0, 0.f); x0 *= x0;
                x1 = fmaxf(x1, 0.f); x1 *= x1;
                x2 = fmaxf(x2, 0.f); x2 *= x2;
                x3 = fmaxf(x3, 0.f); x3 *= x3;
            }
            if (EPI == 0) {
                *(float2*)(Cf + (size_t)row * N + col)       = make_float2(x0, x1);
                *(float2*)(Cf + (size_t)(row + 8) * N + col) = make_float2(x2, x3);
            } else {
                __half2 h01 = __floats2half2_rn(x0, x1);
                __half2 h23 = __floats2half2_rn(x2, x3);
                float2 r01 = __half22float2(h01);
                float2 r23 = __half22float2(h23);
                __half2 l01 = __floats2half2_rn(x0 - r01.x, x1 - r01.y);
                __half2 l23 = __floats2half2_rn(x2 - r23.x, x3 - r23.y);
                *(__half2*)(Ch + (size_t)row * N + col)       = h01;
                *(__half2*)(Ch + (size_t)(row + 8) * N + col) = h23;
                *(__half2*)(Cl + (size_t)row * N + col)       = l01;
                *(__half2*)(Cl + (size_t)(row + 8) * N + col) = l23;
            }
        }
    }
}

// ---------------- GRU: persistent, 128 CTAs x 768 thr (24 warps: 8 dims x 3 gates) ----
__global__ void __launch_bounds__(768, 1) gru_kernel(
    const float* __restrict__ xg, const float* __restrict__ w_hh,
    const float* __restrict__ b_hh, float* __restrict__ states)
{
    __shared__ float hsh[2 * HDIM];
    __shared__ float dres[3][8][2];
    __shared__ float bsh[3][8];
    const int tid = threadIdx.x;
    const int w = tid >> 5, l = tid & 31;
    const int g = w >> 3, j2 = w & 7;
    const int jbase = blockIdx.x * 8;

    // 1 gate-row of w_hh per warp, K split over lanes: 8 float4/lane
    float4 wreg[8];
    {
        const float* wr = w_hh + (size_t)(g * HDIM + jbase + j2) * HDIM + l * 4;
#pragma unroll
        for (int u = 0; u < 8; u++) wreg[u] = *(const float4*)(wr + u * 128);
    }
    if (tid < 24) bsh[tid >> 3][tid & 7] = b_hh[(tid >> 3) * HDIM + jbase + (tid & 7)];

    const unsigned G = gridDim.x;
    for (int t = 0; t < S_LEN; t++) {
        const int p = t & 1;
        if (tid < 512) {
            const float4* hs = (const float4*)(g_hbuf + p * (2 * HDIM));
            ((float4*)hsh)[tid] = __ldcg(hs + tid);
        }
        float xr = 0.f, xz = 0.f, xn = 0.f;
        if (tid < 16) {
            const int b = tid >> 3, jj = tid & 7;
            const float* xp = xg + (size_t)(b * S_LEN + t) * (3 * HDIM) + jbase + jj;
            xr = xp[0]; xz = xp[HDIM]; xn = xp[2 * HDIM];
        }
        __syncthreads();

        float a0 = 0.f, a1 = 0.f;
#pragma unroll
        for (int u = 0; u < 8; u++) {
            float4 h0 = *(const float4*)&hsh[u * 128 + l * 4];
            float4 h1 = *(const float4*)&hsh[HDIM + u * 128 + l * 4];
            float4 ww = wreg[u];
            a0 += ww.x * h0.x + ww.y * h0.y + ww.z * h0.z + ww.w * h0.w;
            a1 += ww.x * h1.x + ww.y * h1.y + ww.z * h1.z + ww.w * h1.w;
        }
#pragma unroll
        for (int off = 16; off > 0; off >>= 1) {
            a0 += __shfl_xor_sync(0xffffffffu, a0, off);
            a1 += __shfl_xor_sync(0xffffffffu, a1, off);
        }
        if (l == 0) { dres[g][j2][0] = a0; dres[g][j2][1] = a1; }
        __syncthreads();

        if (tid < 16) {
            const int b = tid >> 3, jj = tid & 7;
            float hr = dres[0][jj][b] + bsh[0][jj];
            float hz = dres[1][jj][b] + bsh[1][jj];
            float hn = dres[2][jj][b] + bsh[2][jj];
            float r = 1.f / (1.f + expf(-(xr + hr)));
            float z = 1.f / (1.f + expf(-(xz + hz)));
            float n = tanhf(xn + r * hn);
            float hold = hsh[b * HDIM + jbase + jj];
            float hnew = (1.f - z) * n + z * hold;
            __stcg(&g_hbuf[(p ^ 1) * (2 * HDIM) + b * HDIM + jbase + jj], hnew);
            states[(size_t)(b * S_LEN + t) * HDIM + jbase + jj] = hnew;
        }
        __syncthreads();

        // global barrier: counter + release flag (read-mostly spin target)
        if (tid == 0) {
            __threadfence();
            unsigned arr = atomicAdd(&g_bar, 1u);
            if (arr == (unsigned)(t + 1) * G - 1u) {
                *((volatile unsigned*)&g_rel) = (unsigned)(t + 1);
            } else {
                while (*((volatile unsigned*)&g_rel) < (unsigned)(t + 1)) { }
            }
            __threadfence();
        }
        __syncthreads();
    }
}

// ---------------- LayerNorm + gate (emits split-fp16 ns) ----------------
__global__ void __launch_bounds__(256) ln_gate_kernel(
    const float* __restrict__ states, const float* __restrict__ ln_g,
    const float* __restrict__ ln_b, const float* __restrict__ wg,
    const float* __restrict__ bg, __half* __restrict__ nsh, __half* __restrict__ nsl,
    float* __restrict__ gate)
{
    __shared__ float red[3][8];
    const int row = blockIdx.x;
    const int tid = threadIdx.x;
    const float4 xv = ((const float4*)(states + (size_t)row * HDIM))[tid];
    const float4 wv = ((const float4*)wg)[tid];
    float s  = xv.x + xv.y + xv.z + xv.w;
    float sq = xv.x * xv.x + xv.y * xv.y + xv.z * xv.z + xv.w * xv.w;
    float wd = xv.x * wv.x + xv.y * wv.y + xv.z * wv.z + xv.w * wv.w;
#pragma unroll
    for (int off = 16; off > 0; off >>= 1) {
        s  += __shfl_xor_sync(0xffffffffu, s,  off);
        sq += __shfl_xor_sync(0xffffffffu, sq, off);
        wd += __shfl_xor_sync(0xffffffffu, wd, off);
    }
    if ((tid & 31) == 0) { red[0][tid >> 5] = s; red[1][tid >> 5] = sq; red[2][tid >> 5] = wd; }
    __syncthreads();
    s = 0.f; sq = 0.f; wd = 0.f;
#pragma unroll
    for (int u = 0; u < 8; u++) { s += red[0][u]; sq += red[1][u]; wd += red[2][u]; }
    const float mu = s * (1.f / HDIM);
    const float var = sq * (1.f / HDIM) - mu * mu;
    const float rstd = rsqrtf(var + 1e-5f);
    const float4 gv = ((const float4*)ln_g)[tid];
    const float4 bv = ((const float4*)ln_b)[tid];
    float4 o;
    o.x = (xv.x - mu) * rstd * gv.x + bv.x;
    o.y = (xv.y - mu) * rstd * gv.y + bv.y;
    o.z = (xv.z - mu) * rstd * gv.z + bv.z;
    o.w = (xv.w - mu) * rstd * gv.w + bv.w;
    __half2 h01 = __floats2half2_rn(o.x, o.y);
    __half2 h23 = __floats2half2_rn(o.z, o.w);
    float2 r01 = __half22float2(h01);
    float2 r23 = __half22float2(h23);
    __half2 l01 = __floats2half2_rn(o.x - r01.x, o.y - r01.y);
    __half2 l23 = __floats2half2_rn(o.z - r23.x, o.w - r23.y);
    __half2* nh = (__half2*)(nsh + (size_t)row * HDIM) + tid * 2;
    __half2* nl = (__half2*)(nsl + (size_t)row * HDIM) + tid * 2;
    nh[0] = h01; nh[1] = h23;
    nl[0] = l01; nl[1] = l23;
    if (tid == 0) gate[row] = 1.f / (1.f + expf(-(wd + bg[0])));
}

// ---------------- q/k projection ----------------
__global__ void __launch_bounds__(256) qk_kernel(
    const float* __restrict__ states,
    const float* __restrict__ wq, const float* __restrict__ bq,
    const float* __restrict__ wk, const float* __restrict__ bk,
    float* __restrict__ qout, float* __restrict__ kout)
{
    const float* W    = blockIdx.y ? wk : wq;
    const float* bias = blockIdx.y ? bk : bq;
    float* out        = blockIdx.y ? kout : qout;
    __shared__ float As[16][20];
    __shared__ float Ws[16][128];
    const int tid = threadIdx.x;
    const int m0 = blockIdx.x * 16;
    const int tm = tid >> 4;
    const int tn0 = (tid & 15) * 8;
    float acc[8] = {0.f, 0.f, 0.f, 0.f, 0.f, 0.f, 0.f, 0.f};

    for (int k0 = 0; k0 < HDIM; k0 += 16) {
        {
            const int n = tid >> 1;
            const int ks = (tid & 1) * 8;
            const float* wp = W + (size_t)n * HDIM + k0 + ks;
            float4 w0 = *(const float4*)wp;
            float4 w1 = *(const float4*)(wp + 4);
            Ws[ks + 0][n] = w0.x; Ws[ks + 1][n] = w0.y; Ws[ks + 2][n] = w0.z; Ws[ks + 3][n] = w0.w;
            Ws[ks + 4][n] = w1.x; Ws[ks + 5][n] = w1.y; Ws[ks + 6][n] = w1.z; Ws[ks + 7][n] = w1.w;
        }
        if (tid < 64) {
            const int m = tid >> 2;
            const int ks = (tid & 3) * 4;
            float4 a = *(const float4*)(states + (size_t)(m0 + m) * HDIM + k0 + ks);
            As[m][ks] = a.x; As[m][ks + 1] = a.y; As[m][ks + 2] = a.z; As[m][ks + 3] = a.w;
        }
        __syncthreads();
#pragma unroll
        for (int kk = 0; kk < 16; kk++) {
            float a = As[tm][kk];
            float4 b0 = *(const float4*)&Ws[kk][tn0];
            float4 b1 = *(const float4*)&Ws[kk][tn0 + 4];
            acc[0] += a * b0.x; acc[1] += a * b0.y; acc[2] += a * b0.z; acc[3] += a * b0.w;
            acc[4] += a * b1.x; acc[5] += a * b1.y; acc[6] += a * b1.z; acc[7] += a * b1.w;
        }
        __syncthreads();
    }
    float4 o0 = make_float4(acc[0] + bias[tn0 + 0], acc[1] + bias[tn0 + 1],
                            acc[2] + bias[tn0 + 2], acc[3] + bias[tn0 + 3]);
    float4 o1 = make_float4(acc[4] + bias[tn0 + 4], acc[5] + bias[tn0 + 5],
                            acc[6] + bias[tn0 + 6], acc[7] + bias[tn0 + 7]);
    float4* op = (float4*)(out + (size_t)(m0 + tm) * MDIM + tn0);
    op[0] = o0; op[1] = o1;
}

// ---------------- attention scores + softmax + gated scatter-add ----------
__global__ void __launch_bounds__(256) attn_scatter_kernel(
    const float* __restrict__ q, const float* __restrict__ k,
    const float* __restrict__ gate, const int* __restrict__ ids,
    const float* __restrict__ mscale, float* __restrict__ logits)
{
    const int row = blockIdx.x;
    const int i = row & (S_LEN - 1);
    const int b = row >> 10;
    if (i == 0) return;
    __shared__ float qs[MDIM];
    __shared__ float sc[S_LEN];
    __shared__ float red[8];
    const int tid = threadIdx.x;
    if (tid < 32) ((float4*)qs)[tid] = ((const float4*)(q + (size_t)row * MDIM))[tid];
    __syncthreads();

    float lmax = -3.402823466e38f;
    for (int j = tid; j < i; j += 256) {
        const float4* kr = (const float4*)(k + (size_t)(b * S_LEN + j) * MDIM);
        float acc = 0.f;
#pragma unroll
        for (int m = 0; m < 32; m++) {
            float4 kv = kr[m];
            float4 qv = ((const float4*)qs)[m];
            acc += kv.x * qv.x + kv.y * qv.y + kv.z * qv.z + kv.w * qv.w;
        }
        acc *= 0.08838834764831845f;
        sc[j] = acc;
        lmax = fmaxf(lmax, acc);
    }
#pragma unroll
    for (int off = 16; off > 0; off >>= 1)
        lmax = fmaxf(lmax, __shfl_xor_sync(0xffffffffu, lmax, off));
    if ((tid & 31) == 0) red[tid >> 5] = lmax;
    __syncthreads();
    float mx = -3.402823466e38f;
#pragma unroll
    for (int u = 0; u < 8; u++) mx = fmaxf(mx, red[u]);
    __syncthreads();

    float ls = 0.f;
    for (int j = tid; j < i; j += 256) {
        float e = expf(sc[j] - mx);
        sc[j] = e;
        ls += e;
    }
#pragma unroll
    for (int off = 16; off > 0; off >>= 1)
        ls += __shfl_xor_sync(0xffffffffu, ls, off);
    if ((tid & 31) == 0) red[tid >> 5] = ls;
    __syncthreads();
    float tot = 0.f;
#pragma unroll
    for (int u = 0; u < 8; u++) tot += red[u];

    const float coeff = gate[row] * mscale[0] / fmaxf(tot, 1e-6f);
    float* lrow = logits + (size_t)row * VDIM;
    const int* idrow = ids + b * S_LEN;
    for (int j = tid; j < i; j += 256)
        atomicAdd(lrow + idrow[j], sc[j] * coeff);
}

// ---------------- launch ----------------
extern "C" void kernel_launch(void* const* d_in, const int* in_sizes, int n_in,
                              void* d_out, int out_size)
{
    const int*   ids    = (const int*)  d_in[0];
    const float* emb    = (const float*)d_in[1];
    const float* w_ih   = (const float*)d_in[2];
    const float* b_ih   = (const float*)d_in[3];
    const float* w_hh   = (const float*)d_in[4];
    const float* b_hh   = (const float*)d_in[5];
    const float* ln_g   = (const float*)d_in[6];
    const float* ln_b   = (const float*)d_in[7];
    const float* wq     = (const float*)d_in[8];
    const float* bq     = (const float*)d_in[9];
    const float* wk     = (const float*)d_in[10];
    const float* bk     = (const float*)d_in[11];
    const float* wg     = (const float*)d_in[12];
    const float* bg     = (const float*)d_in[13];
    const float* w_fc   = (const float*)d_in[14];
    const float* b_fc   = (const float*)d_in[15];
    const float* w_pr   = (const float*)d_in[16];
    const float* b_pr   = (const float*)d_in[17];
    const float* obias  = (const float*)d_in[18];
    const float* mscale = (const float*)d_in[19];
    float* out = (float*)d_out;

    float *xg, *states, *qv, *kv, *gate;
    __half *embh, *embl, *wihh, *wihl, *wfch, *wfcl, *wprh, *wprl;
    __half *nsh, *nsl, *hfh, *hfl, *baseh, *basel;
    cudaGetSymbolAddress((void**)&xg,     g_xg);
    cudaGetSymbolAddress((void**)&states, g_states);
    cudaGetSymbolAddress((void**)&qv,     g_q);
    cudaGetSymbolAddress((void**)&kv,     g_k);
    cudaGetSymbolAddress((void**)&gate,   g_gate);
    cudaGetSymbolAddress((void**)&embh,   g_emb_h);
    cudaGetSymbolAddress((void**)&embl,   g_emb_l);
    cudaGetSymbolAddress((void**)&wihh,   g_wih_h);
    cudaGetSymbolAddress((void**)&wihl,   g_wih_l);
    cudaGetSymbolAddress((void**)&wfch,   g_wfc_h);
    cudaGetSymbolAddress((void**)&wfcl,   g_wfc_l);
    cudaGetSymbolAddress((void**)&wprh,   g_wpr_h);
    cudaGetSymbolAddress((void**)&wprl,   g_wpr_l);
    cudaGetSymbolAddress((void**)&nsh,    g_ns_h);
    cudaGetSymbolAddress((void**)&nsl,    g_ns_l);
    cudaGetSymbolAddress((void**)&hfh,    g_hf_h);
    cudaGetSymbolAddress((void**)&hfl,    g_hf_l);
    cudaGetSymbolAddress((void**)&baseh,  g_base_h);
    cudaGetSymbolAddress((void**)&basel,  g_base_l);

    cudaFuncSetAttribute(mma_gemm<3, 0, true>,  cudaFuncAttributeMaxDynamicSharedMemorySize, MT_SMEM_TOTAL);
    cudaFuncSetAttribute(mma_gemm<3, 1, false>, cudaFuncAttributeMaxDynamicSharedMemorySize, MT_SMEM_TOTAL);
    cudaFuncSetAttribute(mma_gemm<3, 2, false>, cudaFuncAttributeMaxDynamicSharedMemorySize, MT_SMEM_TOTAL);
    cudaFuncSetAttribute(mma_gemm<2, 0, false>, cudaFuncAttributeMaxDynamicSharedMemorySize, MT_SMEM_TOTAL);

    // 0) split weights + embedding to fp16 hi/lo
    split_kernel<<<2048, 256>>>((const float4*)emb,  (uint2*)embh, (uint2*)embl, VDIM * EDIM / 4);
    split_kernel<<<512, 256>>>((const float4*)w_ih, (uint2*)wihh, (uint2*)wihl, 3 * HDIM * EDIM / 4);
    split_kernel<<<512, 256>>>((const float4*)w_fc, (uint2*)wfch, (uint2*)wfcl, 4 * EDIM * HDIM / 4);
    split_kernel<<<512, 256>>>((const float4*)w_pr, (uint2*)wprh, (uint2*)wprl, EDIM * 4 * EDIM / 4);

    // 1) xg = emb[ids] @ w_ih^T + b_ih     (2048 x 3072, K=512) -> fp32
    mma_gemm<3, 0, true><<<dim3(24, 16), 256, MT_SMEM_TOTAL>>>(
        embh, embl, wihh, wihl, b_ih, xg, nullptr, nullptr, 3072, 512, ids);
    // 2) reset barrier + h0
    init_kernel<<<16, 256>>>();
    // 3) GRU scan
    gru_kernel<<<128, 768>>>(xg, w_hh, b_hh, states);
    // 4) LayerNorm + gate -> split ns
    ln_gate_kernel<<<BATCH * S_LEN, 256>>>(states, ln_g, ln_b, wg, bg, nsh, nsl, gate);
    // 5) q / k projections
    qk_kernel<<<dim3(128, 2), 256>>>(states, wq, bq, wk, bk, qv, kv);
    // 6) hf = relu(ns @ w_fc^T + b_fc)^2   (2048 x 2048, K=1024) -> split hf
    mma_gemm<3, 1, false><<<dim3(16, 16), 256, MT_SMEM_TOTAL>>>(
        nsh, nsl, wfch, wfcl, b_fc, nullptr, hfh, hfl, 2048, 1024, nullptr);
    // 7) base = hf @ w_pr^T + b_pr         (2048 x 512, K=2048) -> split base
    mma_gemm<3, 2, false><<<dim3(4, 16), 256, MT_SMEM_TOTAL>>>(
        hfh, hfl, wprh, wprl, b_pr, nullptr, baseh, basel, 512, 2048, nullptr);
    // 8) logits = base @ emb^T + out_bias  (2048 x 32000, K=512), 2-term -> fp32 out
    mma_gemm<2, 0, false><<<dim3(250, 16), 256, MT_SMEM_TOTAL>>>(
        baseh, basel, embh, nullptr, obias, out, nullptr, nullptr, 32000, 512, nullptr);
    // 9) attention softmax + gated scatter-add
    attn_scatter_kernel<<<BATCH * S_LEN, 256>>>(qv, kv, gate, ids, mscale, out);
}